// round 12
// baseline (speedup 1.0000x reference)
#include <cuda_runtime.h>
#include <cuda_fp16.h>
#include <math.h>

#define NODES 100000
#define EDGES 1600000
#define SCAN_NB 98   // ceil(100000/1024)

typedef unsigned long long ull;

// ---------------- scratch (device globals: allocation-free) ----------------
__device__ int     g_deg[NODES];
__device__ int     g_fill[NODES];
__device__ int     g_ptr[NODES + 1];
__device__ int     g_aggpub[SCAN_NB];
__device__ int     g_csr[EDGES];
__device__ float   g_inv[NODES];
__device__ float   g_h0[NODES * 64];
__device__ float   g_h1[NODES * 64];
__device__ __half2 g_hx[NODES * 16];   // fp16 copy of x  [N][16] half2
__device__ __half2 g_hh0[NODES * 32];  // fp16 hidden     [N][32] half2
__device__ __half2 g_hh1[NODES * 32];
// packed weights: entry [i*32+l] = (Wn[i][2l+p], Wr[i][2l+p]) for p=0(w0)/1(w1)
__device__ ull     g_w0[3][2048];
__device__ ull     g_w1[3][2048];
__device__ ull     g_wp[2048];         // (Wp1[i][2l], Wp1[i][2l+1])

// ---------------- packed f32x2 FMA (FFMA2 — only reachable via PTX) --------
__device__ __forceinline__ ull fma2(ull a, ull b, ull c) {
    ull d;
    asm("fma.rn.f32x2 %0, %1, %2, %3;" : "=l"(d) : "l"(a), "l"(b), "l"(c));
    return d;
}
__device__ __forceinline__ ull pack2(float x, float y) {
    float2 t = make_float2(x, y);
    return *(ull*)&t;
}
__device__ __forceinline__ float2 unpack2(ull v) { return *(float2*)&v; }

__device__ __forceinline__ void acc16B(uint4 v, float* f) {
    __half2 h0 = *(__half2*)&v.x, h1 = *(__half2*)&v.y;
    __half2 h2 = *(__half2*)&v.z, h3 = *(__half2*)&v.w;
    float2 a = __half22float2(h0), b = __half22float2(h1);
    float2 c = __half22float2(h2), d = __half22float2(h3);
    f[0] += a.x; f[1] += a.y; f[2] += b.x; f[3] += b.y;
    f[4] += c.x; f[5] += c.y; f[6] += d.x; f[7] += d.y;
}

// ---------------- weight pre-pack (grid: 8 x 256 = 2048 threads) ----------
__global__ void k_pack(const float* __restrict__ Wn0, const float* __restrict__ Wr0,
                       const float* __restrict__ Wn1, const float* __restrict__ Wr1,
                       const float* __restrict__ Wn2, const float* __restrict__ Wr2,
                       const float* __restrict__ Wp1) {
    int idx = blockIdx.x * 256 + threadIdx.x;   // 0..2047
    int i = idx >> 5, l = idx & 31;
    if (idx < 1024) {
        g_w0[0][idx] = pack2(Wn0[i * 64 + 2 * l],     Wr0[i * 64 + 2 * l]);
        g_w1[0][idx] = pack2(Wn0[i * 64 + 2 * l + 1], Wr0[i * 64 + 2 * l + 1]);
    }
    g_w0[1][idx] = pack2(Wn1[i * 64 + 2 * l],     Wr1[i * 64 + 2 * l]);
    g_w1[1][idx] = pack2(Wn1[i * 64 + 2 * l + 1], Wr1[i * 64 + 2 * l + 1]);
    g_w0[2][idx] = pack2(Wn2[i * 64 + 2 * l],     Wr2[i * 64 + 2 * l]);
    g_w1[2][idx] = pack2(Wn2[i * 64 + 2 * l + 1], Wr2[i * 64 + 2 * l + 1]);
    g_wp[idx]    = pack2(Wp1[i * 64 + 2 * l],     Wp1[i * 64 + 2 * l + 1]);
}

// ---------------- cvt x->fp16 + degree histogram (merged) ----------------
__global__ void k_cvthist(const float2* __restrict__ x2, __half2* __restrict__ hx,
                          const int* __restrict__ dst) {
    int i = blockIdx.x * blockDim.x + threadIdx.x;
    if (i < NODES * 16) {
        float2 v = x2[i];
        hx[i] = __floats2half2_rn(v.x, v.y);
    }
    if (i < EDGES) atomicAdd(&g_deg[dst[i]], 1);
}

// single-pass scan: all 98 blocks resident; block b sums predecessors' aggregates
__global__ void k_scanlb() {
    __shared__ int sh[1024];
    __shared__ int spart[32];
    __shared__ int s_pref;
    int tid = threadIdx.x, b = blockIdx.x;
    int i = b * 1024 + tid;
    int v = (i < NODES) ? g_deg[i] : 0;
    sh[tid] = v;
    __syncthreads();
    for (int off = 1; off < 1024; off <<= 1) {
        int t = (tid >= off) ? sh[tid - off] : 0;
        __syncthreads();
        sh[tid] += t;
        __syncthreads();
    }
    if (tid == 1023) atomicExch(&g_aggpub[b], sh[1023]);   // publish aggregate

    int myv = 0;
    if (tid < b) {                                          // b <= 97 < 1024
        int t;
        do { t = atomicAdd(&g_aggpub[tid], 0); } while (t < 0);
        myv = t;
    }
#pragma unroll
    for (int off = 16; off; off >>= 1) myv += __shfl_xor_sync(0xffffffffu, myv, off);
    if ((tid & 31) == 0) spart[tid >> 5] = myv;
    __syncthreads();
    if (tid == 0) {
        int s = 0;
#pragma unroll
        for (int wdx = 0; wdx < 32; wdx++) s += spart[wdx];
        s_pref = s;
    }
    __syncthreads();
    if (i < NODES) {
        g_ptr[i] = s_pref + sh[tid] - v;                    // exclusive prefix
        g_inv[i] = (v > 0) ? (1.0f / (float)v) : 0.0f;
    }
    if (i == 0) g_ptr[NODES] = EDGES;
}

__global__ void k_fill(const int* __restrict__ src, const int* __restrict__ dst) {
    int e = blockIdx.x * blockDim.x + threadIdx.x;
    if (e < EDGES) {
        int d = dst[e];
        int pos = g_ptr[d] + atomicAdd(&g_fill[d], 1);
        g_csr[pos] = src[e];
    }
}

// ================= fused SAGE layer (barrier-free) =================
// 256 threads = 8 warps x 8 nodes = 64 nodes/block. No __syncthreads:
// every warp gathers + GEMMs + stores only its own 8 nodes; weights via __ldg.
template <int DIN, bool RELU, bool PRED>
__global__ void __launch_bounds__(256, 4) k_sage(const float* __restrict__ hin,
                                                 const __half2* __restrict__ hhin,
                                                 const ull* __restrict__ w0p,
                                                 const ull* __restrict__ w1p,
                                                 const float* __restrict__ bn,
                                                 const float* __restrict__ bp1,
                                                 const float* __restrict__ Wp2,
                                                 const float* __restrict__ bp2,
                                                 float* __restrict__ hout,
                                                 __half2* __restrict__ hhout,
                                                 float* __restrict__ pred_out) {
    extern __shared__ ull sAH[];     // [64][DIN] (agg, own) per [node][i]

    int tid = threadIdx.x, w = tid >> 5, lane = tid & 31;
    int sb = w * 8;
    int n0 = blockIdx.x * 64;

    const uint4* __restrict__ hv = (const uint4*)hhin;

    // ---- Phase A: aggregate 8 nodes per warp, vectorized gather ----
#pragma unroll 1
    for (int s = 0; s < 8; s++) {
        int sl = sb + s;
        int ng = n0 + sl;
        if (ng >= NODES) break;
        int beg = g_ptr[ng], end = g_ptr[ng + 1];
        float iv = g_inv[ng];
        float f[8];
#pragma unroll
        for (int m = 0; m < 8; m++) f[m] = 0.f;

        if (DIN == 64) {
            int c   = lane & 7;    // 16B chunk of 128B row
            int esl = lane >> 3;   // edge slot 0..3
            int k = beg;
            for (; k + 15 < end; k += 16) {
                int id0 = __ldg(&g_csr[k +  0 + esl]);
                int id1 = __ldg(&g_csr[k +  4 + esl]);
                int id2 = __ldg(&g_csr[k +  8 + esl]);
                int id3 = __ldg(&g_csr[k + 12 + esl]);
                uint4 v0 = __ldg(&hv[id0 * 8 + c]);
                uint4 v1 = __ldg(&hv[id1 * 8 + c]);
                uint4 v2 = __ldg(&hv[id2 * 8 + c]);
                uint4 v3 = __ldg(&hv[id3 * 8 + c]);
                acc16B(v0, f); acc16B(v1, f); acc16B(v2, f); acc16B(v3, f);
            }
            for (; k < end; k += 4) {
                int e = k + esl;
                if (e < end) {
                    int id = __ldg(&g_csr[e]);
                    acc16B(__ldg(&hv[id * 8 + c]), f);
                }
            }
            // fold 4 edge-slots
#pragma unroll
            for (int off = 8; off <= 16; off <<= 1)
#pragma unroll
                for (int m = 0; m < 8; m++)
                    f[m] += __shfl_xor_sync(0xffffffffu, f[m], off);
            if (lane < 8) {
                float4 o0 = ((const float4*)hin)[ng * 16 + 2 * c];
                float4 o1 = ((const float4*)hin)[ng * 16 + 2 * c + 1];
                ull* dstp = &sAH[sl * 64 + 8 * c];
                dstp[0] = pack2(f[0] * iv, o0.x);
                dstp[1] = pack2(f[1] * iv, o0.y);
                dstp[2] = pack2(f[2] * iv, o0.z);
                dstp[3] = pack2(f[3] * iv, o0.w);
                dstp[4] = pack2(f[4] * iv, o1.x);
                dstp[5] = pack2(f[5] * iv, o1.y);
                dstp[6] = pack2(f[6] * iv, o1.z);
                dstp[7] = pack2(f[7] * iv, o1.w);
            }
        } else {  // DIN == 32: 64B rows, 4 chunks, 8 edges per LDG.128 pass
            int c   = lane & 3;    // 16B chunk of 64B row
            int esl = lane >> 2;   // edge slot 0..7
            int k = beg;
            for (; k + 15 < end; k += 16) {
                int id0 = __ldg(&g_csr[k + 0 + esl]);
                int id1 = __ldg(&g_csr[k + 8 + esl]);
                uint4 v0 = __ldg(&hv[id0 * 4 + c]);
                uint4 v1 = __ldg(&hv[id1 * 4 + c]);
                acc16B(v0, f); acc16B(v1, f);
            }
            for (; k < end; k += 8) {
                int e = k + esl;
                if (e < end) {
                    int id = __ldg(&g_csr[e]);
                    acc16B(__ldg(&hv[id * 4 + c]), f);
                }
            }
#pragma unroll
            for (int off = 4; off <= 16; off <<= 1)
#pragma unroll
                for (int m = 0; m < 8; m++)
                    f[m] += __shfl_xor_sync(0xffffffffu, f[m], off);
            if (lane < 4) {
                float4 o0 = ((const float4*)hin)[ng * 8 + 2 * c];
                float4 o1 = ((const float4*)hin)[ng * 8 + 2 * c + 1];
                ull* dstp = &sAH[sl * 32 + 8 * c];
                dstp[0] = pack2(f[0] * iv, o0.x);
                dstp[1] = pack2(f[1] * iv, o0.y);
                dstp[2] = pack2(f[2] * iv, o0.z);
                dstp[3] = pack2(f[3] * iv, o0.w);
                dstp[4] = pack2(f[4] * iv, o1.x);
                dstp[5] = pack2(f[5] * iv, o1.y);
                dstp[6] = pack2(f[6] * iv, o1.z);
                dstp[7] = pack2(f[7] * iv, o1.w);
            }
        }
    }
    __syncwarp();    // warp-private sAH rows: warp-level visibility suffices

    // ---- Phase B: GEMM, lane owns output features (2*lane, 2*lane+1) ----
    ull acc0[8], acc1[8];
#pragma unroll
    for (int s = 0; s < 8; s++) { acc0[s] = 0ull; acc1[s] = 0ull; }

#pragma unroll 4
    for (int i = 0; i < DIN; i++) {
        ull w0 = __ldg(&w0p[i * 32 + lane]);
        ull w1 = __ldg(&w1p[i * 32 + lane]);
#pragma unroll
        for (int s = 0; s < 8; s++) {
            ull ah = sAH[(sb + s) * DIN + i];   // broadcast LDS.64
            acc0[s] = fma2(ah, w0, acc0[s]);
            acc1[s] = fma2(ah, w1, acc1[s]);
        }
    }

    float2 b2 = ((const float2*)bn)[lane];
    float rx[8], ry[8];
#pragma unroll
    for (int s = 0; s < 8; s++) {
        float2 v0 = unpack2(acc0[s]);
        float2 v1 = unpack2(acc1[s]);
        rx[s] = v0.x + v0.y + b2.x;
        ry[s] = v1.x + v1.y + b2.y;
        if (RELU) { rx[s] = fmaxf(rx[s], 0.f); ry[s] = fmaxf(ry[s], 0.f); }
    }

    if (!PRED) {
#pragma unroll
        for (int s = 0; s < 8; s++) {
            int ng = n0 + sb + s;
            if (ng < NODES) {
                ((float2*)hout)[ng * 32 + lane] = make_float2(rx[s], ry[s]);
                hhout[ng * 32 + lane] = __floats2half2_rn(rx[s], ry[s]);
            }
        }
        return;
    }

    // ---- PRED (warp-private): sigmoid(relu(h@Wp1+bp1)@Wp2 + bp2) ----
    __syncwarp();
    float* sH = (float*)(sAH + sb * 64);   // warp's own 4KB slice, need 2KB
#pragma unroll
    for (int s = 0; s < 8; s++) {
        sH[s * 64 + 2 * lane]     = rx[s];
        sH[s * 64 + 2 * lane + 1] = ry[s];
    }
    __syncwarp();

    float2 bb = ((const float2*)bp1)[lane];
    float2 v2 = __ldg((const float2*)Wp2 + lane);
    float  vb = __ldg(bp2);
#pragma unroll 1
    for (int s = 0; s < 8; s++) {
        float ax = bb.x, ay = bb.y;
#pragma unroll 8
        for (int i = 0; i < 64; i++) {
            float hh = sH[s * 64 + i];
            float2 wv = unpack2(__ldg(&g_wp[i * 32 + lane]));
            ax += hh * wv.x;
            ay += hh * wv.y;
        }
        ax = fmaxf(ax, 0.f);
        ay = fmaxf(ay, 0.f);
        float z = ax * v2.x + ay * v2.y;
#pragma unroll
        for (int off = 16; off; off >>= 1) z += __shfl_xor_sync(0xffffffffu, z, off);
        int ng = n0 + sb + s;
        if (lane == 0 && ng < NODES) pred_out[ng] = 1.f / (1.f + expf(-(z + vb)));
    }
}

// ---------------- launch ----------------
extern "C" void kernel_launch(void* const* d_in, const int* in_sizes, int n_in,
                              void* d_out, int out_size) {
    const float* x   = (const float*)d_in[0];
    const int*   ei  = (const int*)d_in[1];
    const int*   src = ei;
    const int*   dst = ei + EDGES;
    const float* Wn0 = (const float*)d_in[2];
    const float* bn0 = (const float*)d_in[3];
    const float* Wr0 = (const float*)d_in[4];
    const float* Wn1 = (const float*)d_in[5];
    const float* bn1 = (const float*)d_in[6];
    const float* Wr1 = (const float*)d_in[7];
    const float* Wn2 = (const float*)d_in[8];
    const float* bn2 = (const float*)d_in[9];
    const float* Wr2 = (const float*)d_in[10];
    const float* Wp1 = (const float*)d_in[11];
    const float* bp1 = (const float*)d_in[12];
    const float* Wp2 = (const float*)d_in[13];
    const float* bp2 = (const float*)d_in[14];
    float* out = (float*)d_out;

    float *pH0, *pH1;
    __half2 *pHX, *pHH0, *pHH1;
    int *pDeg, *pFill, *pAggpub;
    ull *pW0, *pW1;
    cudaGetSymbolAddress((void**)&pH0, g_h0);
    cudaGetSymbolAddress((void**)&pH1, g_h1);
    cudaGetSymbolAddress((void**)&pHX, g_hx);
    cudaGetSymbolAddress((void**)&pHH0, g_hh0);
    cudaGetSymbolAddress((void**)&pHH1, g_hh1);
    cudaGetSymbolAddress((void**)&pDeg, g_deg);
    cudaGetSymbolAddress((void**)&pFill, g_fill);
    cudaGetSymbolAddress((void**)&pAggpub, g_aggpub);
    cudaGetSymbolAddress((void**)&pW0, g_w0);
    cudaGetSymbolAddress((void**)&pW1, g_w1);

    cudaMemsetAsync(pDeg, 0, NODES * sizeof(int));
    cudaMemsetAsync(pFill, 0, NODES * sizeof(int));
    cudaMemsetAsync(pAggpub, 0xFF, SCAN_NB * sizeof(int));   // -1 sentinel

    // prep: pack weights; x->fp16 + hist; scan; fill
    k_pack<<<8, 256>>>(Wn0, Wr0, Wn1, Wr1, Wn2, Wr2, Wp1);
    k_cvthist<<<(EDGES + 255) / 256, 256>>>((const float2*)x, pHX, dst);
    k_scanlb<<<SCAN_NB, 1024>>>();
    k_fill<<<(EDGES + 255) / 256, 256>>>(src, dst);

    const int GRID = (NODES + 63) / 64;   // 1563

    // layer 0: 32 -> 64, relu (fp16 vector gather of x, fp32 own)
    k_sage<32, true,  false><<<GRID, 256, 64 * 32 * 8>>>(x, pHX,
            pW0 + 0 * 2048, pW1 + 0 * 2048, bn0,
            nullptr, nullptr, nullptr, pH0, pHH0, nullptr);
    // layer 1: 64 -> 64, relu
    k_sage<64, true,  false><<<GRID, 256, 64 * 64 * 8>>>(pH0, pHH0,
            pW0 + 1 * 2048, pW1 + 1 * 2048, bn1,
            nullptr, nullptr, nullptr, pH1, pHH1, nullptr);
    // layer 2: 64 -> 64, no relu, predictor fused (warp-private)
    k_sage<64, false, true ><<<GRID, 256, 64 * 64 * 8>>>(pH1, pHH1,
            pW0 + 2 * 2048, pW1 + 2 * 2048, bn2,
            bp1, Wp2, bp2, nullptr, nullptr, out);

    (void)in_sizes; (void)n_in; (void)out_size;
}

// round 13
// speedup vs baseline: 1.0167x; 1.0167x over previous
#include <cuda_runtime.h>
#include <cuda_fp16.h>
#include <math.h>

#define NODES 100000
#define EDGES 1600000
#define SCAN_NB 98   // ceil(100000/1024)

typedef unsigned long long ull;

// ---------------- scratch (device globals: allocation-free) ----------------
__device__ int     g_deg[NODES];
__device__ int     g_fill[NODES];
__device__ int     g_ptr[NODES + 1];
__device__ int     g_aggpub[SCAN_NB];
__device__ int     g_csr[EDGES];
__device__ float   g_inv[NODES];
__device__ float   g_h0[NODES * 64];
__device__ float   g_h1[NODES * 64];
__device__ __half2 g_hx[NODES * 16];   // fp16 copy of x  [N][16] half2
__device__ __half2 g_hh0[NODES * 32];  // fp16 hidden     [N][32] half2
__device__ __half2 g_hh1[NODES * 32];

// ---------------- packed f32x2 FMA (FFMA2 — only reachable via PTX) --------
__device__ __forceinline__ ull fma2(ull a, ull b, ull c) {
    ull d;
    asm("fma.rn.f32x2 %0, %1, %2, %3;" : "=l"(d) : "l"(a), "l"(b), "l"(c));
    return d;
}
__device__ __forceinline__ ull pack2(float x, float y) {
    float2 t = make_float2(x, y);
    return *(ull*)&t;
}
__device__ __forceinline__ float2 unpack2(ull v) { return *(float2*)&v; }

// 2-level fp16 pairwise tree over 8 half2 values, fp32 accumulate.
__device__ __forceinline__ void tree8(const __half2* vv, float& sx, float& sy) {
    __half2 a  = __hadd2(vv[0], vv[1]);
    __half2 b  = __hadd2(vv[2], vv[3]);
    __half2 c  = __hadd2(vv[4], vv[5]);
    __half2 d  = __hadd2(vv[6], vv[7]);
    __half2 ab = __hadd2(a, b);
    __half2 cd = __hadd2(c, d);
    float2 f0 = __half22float2(ab);
    float2 f1 = __half22float2(cd);
    sx += f0.x + f1.x;
    sy += f0.y + f1.y;
}

// ---------------- cvt x->fp16 + degree histogram (merged) ----------------
__global__ void k_cvthist(const float2* __restrict__ x2, __half2* __restrict__ hx,
                          const int* __restrict__ dst) {
    int i = blockIdx.x * blockDim.x + threadIdx.x;
    if (i < NODES * 16) {
        float2 v = x2[i];
        hx[i] = __floats2half2_rn(v.x, v.y);
    }
    if (i < EDGES) atomicAdd(&g_deg[dst[i]], 1);
}

// single-pass scan: all 98 blocks resident; block b sums predecessors' aggregates
__global__ void k_scanlb() {
    __shared__ int sh[1024];
    __shared__ int spart[32];
    __shared__ int s_pref;
    int tid = threadIdx.x, b = blockIdx.x;
    int i = b * 1024 + tid;
    int v = (i < NODES) ? g_deg[i] : 0;
    sh[tid] = v;
    __syncthreads();
    for (int off = 1; off < 1024; off <<= 1) {
        int t = (tid >= off) ? sh[tid - off] : 0;
        __syncthreads();
        sh[tid] += t;
        __syncthreads();
    }
    if (tid == 1023) atomicExch(&g_aggpub[b], sh[1023]);   // publish aggregate

    int myv = 0;
    if (tid < b) {                                          // b <= 97 < 1024
        int t;
        do { t = atomicAdd(&g_aggpub[tid], 0); } while (t < 0);
        myv = t;
    }
#pragma unroll
    for (int off = 16; off; off >>= 1) myv += __shfl_xor_sync(0xffffffffu, myv, off);
    if ((tid & 31) == 0) spart[tid >> 5] = myv;
    __syncthreads();
    if (tid == 0) {
        int s = 0;
#pragma unroll
        for (int wdx = 0; wdx < 32; wdx++) s += spart[wdx];
        s_pref = s;
    }
    __syncthreads();
    if (i < NODES) {
        g_ptr[i] = s_pref + sh[tid] - v;                    // exclusive prefix
        g_inv[i] = (v > 0) ? (1.0f / (float)v) : 0.0f;
    }
    if (i == 0) g_ptr[NODES] = EDGES;
}

__global__ void k_fill(const int* __restrict__ src, const int* __restrict__ dst) {
    int e = blockIdx.x * blockDim.x + threadIdx.x;
    if (e < EDGES) {
        int d = dst[e];
        int pos = g_ptr[d] + atomicAdd(&g_fill[d], 1);
        g_csr[pos] = src[e];
    }
}

// ================= fused SAGE layer (R6 structure + HADD2-tree gather) =====
// 256 threads = 8 warps x 8 nodes = 64 nodes/block. smem weights.
template <int DIN, bool RELU, bool PRED>
__global__ void __launch_bounds__(256) k_sage(const float* __restrict__ hin,
                                              const __half2* __restrict__ hhin,
                                              const float* __restrict__ Wn,
                                              const float* __restrict__ bn,
                                              const float* __restrict__ Wr,
                                              const float* __restrict__ Wp1,
                                              const float* __restrict__ bp1,
                                              const float* __restrict__ Wp2,
                                              const float* __restrict__ bp2,
                                              float* __restrict__ hout,
                                              __half2* __restrict__ hhout,
                                              float* __restrict__ pred_out) {
    extern __shared__ ull dyn[];
    ull* sW0 = dyn;                  // [DIN*32] (Wn[i][2l],   Wr[i][2l])
    ull* sW1 = dyn + DIN * 32;       // [DIN*32] (Wn[i][2l+1], Wr[i][2l+1])
    ull* sAH = dyn + DIN * 64;       // [64*DIN] (agg, own) per [node][i]
    __shared__ float sV[64];

    int tid = threadIdx.x, w = tid >> 5, lane = tid & 31;
    int sb = w * 8;
    int n0 = blockIdx.x * 64;

    // ---- weights ----
    for (int idx = tid; idx < DIN * 32; idx += 256) {
        int i = idx >> 5, l = idx & 31;
        sW0[idx] = pack2(Wn[i * 64 + 2 * l],     Wr[i * 64 + 2 * l]);
        sW1[idx] = pack2(Wn[i * 64 + 2 * l + 1], Wr[i * 64 + 2 * l + 1]);
    }

    // ---- Phase A: aggregate 8 nodes per warp (fp16 tree accumulation) ----
#pragma unroll 1
    for (int s = 0; s < 8; s++) {
        int sl = sb + s;
        int ng = n0 + sl;
        if (ng >= NODES) break;
        int beg = g_ptr[ng], end = g_ptr[ng + 1];
        float iv = g_inv[ng];

        if (DIN == 64) {
            float sx = 0.f, sy = 0.f;
            int k = beg;
            for (; k + 7 < end; k += 8) {
                int id[8];
#pragma unroll
                for (int j = 0; j < 8; j++) id[j] = __ldg(&g_csr[k + j]);
                __half2 vv[8];
#pragma unroll
                for (int j = 0; j < 8; j++) vv[j] = __ldg(&hhin[id[j] * 32 + lane]);
                tree8(vv, sx, sy);
            }
            for (; k < end; k++) {
                float2 f = __half22float2(__ldg(&hhin[__ldg(&g_csr[k]) * 32 + lane]));
                sx += f.x; sy += f.y;
            }
            float2 own = ((const float2*)hin)[ng * 32 + lane];
            sAH[sl * 64 + 2 * lane]     = pack2(sx * iv, own.x);
            sAH[sl * 64 + 2 * lane + 1] = pack2(sy * iv, own.y);
        } else {  // DIN == 32: fp16 rows of 16 half2 (64B); 2 edge subgroups
            int hl  = lane & 15;      // feature-pair index
            int sub = lane >> 4;      // edge subgroup 0/1
            float sx = 0.f, sy = 0.f;
            int k = beg + sub;
            for (; k + 14 < end; k += 16) {
                int id[8];
#pragma unroll
                for (int j = 0; j < 8; j++) id[j] = __ldg(&g_csr[k + 2 * j]);
                __half2 vv[8];
#pragma unroll
                for (int j = 0; j < 8; j++) vv[j] = __ldg(&hhin[id[j] * 16 + hl]);
                tree8(vv, sx, sy);
            }
            for (; k < end; k += 2) {
                float2 f = __half22float2(__ldg(&hhin[__ldg(&g_csr[k]) * 16 + hl]));
                sx += f.x; sy += f.y;
            }
            sx += __shfl_xor_sync(0xffffffffu, sx, 16);
            sy += __shfl_xor_sync(0xffffffffu, sy, 16);
            if (lane < 16) {
                float2 own = ((const float2*)hin)[ng * 16 + hl];
                sAH[sl * 32 + 2 * hl]     = pack2(sx * iv, own.x);
                sAH[sl * 32 + 2 * hl + 1] = pack2(sy * iv, own.y);
            }
        }
    }
    __syncthreads();

    // ---- Phase B: GEMM, lane owns output features (2*lane, 2*lane+1) ----
    ull acc0[8], acc1[8];
#pragma unroll
    for (int s = 0; s < 8; s++) { acc0[s] = 0ull; acc1[s] = 0ull; }

#pragma unroll 4
    for (int i = 0; i < DIN; i++) {
        ull w0 = sW0[i * 32 + lane];
        ull w1 = sW1[i * 32 + lane];
#pragma unroll
        for (int s = 0; s < 8; s++) {
            ull ah = sAH[(sb + s) * DIN + i];   // broadcast LDS.64
            acc0[s] = fma2(ah, w0, acc0[s]);
            acc1[s] = fma2(ah, w1, acc1[s]);
        }
    }

    float2 b2 = ((const float2*)bn)[lane];
    float rx[8], ry[8];
#pragma unroll
    for (int s = 0; s < 8; s++) {
        float2 v0 = unpack2(acc0[s]);
        float2 v1 = unpack2(acc1[s]);
        rx[s] = v0.x + v0.y + b2.x;
        ry[s] = v1.x + v1.y + b2.y;
        if (RELU) { rx[s] = fmaxf(rx[s], 0.f); ry[s] = fmaxf(ry[s], 0.f); }
    }

    if (!PRED) {
#pragma unroll
        for (int s = 0; s < 8; s++) {
            int ng = n0 + sb + s;
            if (ng < NODES) {
                ((float2*)hout)[ng * 32 + lane] = make_float2(rx[s], ry[s]);
                hhout[ng * 32 + lane] = __floats2half2_rn(rx[s], ry[s]);
            }
        }
        return;
    }

    // ---- PRED: sigmoid(relu(h@Wp1+bp1)@Wp2 + bp2) ----
    __syncthreads();                       // all warps done with sW/sAH
    float*  sH  = (float*)sAH;             // [64][64] = 16KB (of 32KB)
    float2* sWp = (float2*)sW0;            // [64][32] = 16KB (of 32KB)

#pragma unroll
    for (int s = 0; s < 8; s++) {
        sH[(sb + s) * 64 + 2 * lane]     = rx[s];
        sH[(sb + s) * 64 + 2 * lane + 1] = ry[s];
    }
    const float2* Wp12 = (const float2*)Wp1;
    for (int idx = tid; idx < 64 * 32; idx += 256) sWp[idx] = Wp12[idx];
    if (tid < 64) sV[tid] = Wp2[tid];
    __syncthreads();

    float2 bb = ((const float2*)bp1)[lane];
    float  vb = bp2[0];
#pragma unroll 1
    for (int s = 0; s < 8; s++) {
        float ax = bb.x, ay = bb.y;
#pragma unroll 8
        for (int i = 0; i < 64; i++) {
            float hh = sH[(sb + s) * 64 + i];
            float2 wv = sWp[i * 32 + lane];
            ax += hh * wv.x;
            ay += hh * wv.y;
        }
        ax = fmaxf(ax, 0.f);
        ay = fmaxf(ay, 0.f);
        float z = ax * sV[2 * lane] + ay * sV[2 * lane + 1];
#pragma unroll
        for (int off = 16; off; off >>= 1) z += __shfl_xor_sync(0xffffffffu, z, off);
        int ng = n0 + sb + s;
        if (lane == 0 && ng < NODES) pred_out[ng] = 1.f / (1.f + expf(-(z + vb)));
    }
}

// ---------------- launch ----------------
extern "C" void kernel_launch(void* const* d_in, const int* in_sizes, int n_in,
                              void* d_out, int out_size) {
    const float* x   = (const float*)d_in[0];
    const int*   ei  = (const int*)d_in[1];
    const int*   src = ei;
    const int*   dst = ei + EDGES;
    const float* Wn0 = (const float*)d_in[2];
    const float* bn0 = (const float*)d_in[3];
    const float* Wr0 = (const float*)d_in[4];
    const float* Wn1 = (const float*)d_in[5];
    const float* bn1 = (const float*)d_in[6];
    const float* Wr1 = (const float*)d_in[7];
    const float* Wn2 = (const float*)d_in[8];
    const float* bn2 = (const float*)d_in[9];
    const float* Wr2 = (const float*)d_in[10];
    const float* Wp1 = (const float*)d_in[11];
    const float* bp1 = (const float*)d_in[12];
    const float* Wp2 = (const float*)d_in[13];
    const float* bp2 = (const float*)d_in[14];
    float* out = (float*)d_out;

    float *pH0, *pH1;
    __half2 *pHX, *pHH0, *pHH1;
    int *pDeg, *pFill, *pAggpub;
    cudaGetSymbolAddress((void**)&pH0, g_h0);
    cudaGetSymbolAddress((void**)&pH1, g_h1);
    cudaGetSymbolAddress((void**)&pHX, g_hx);
    cudaGetSymbolAddress((void**)&pHH0, g_hh0);
    cudaGetSymbolAddress((void**)&pHH1, g_hh1);
    cudaGetSymbolAddress((void**)&pDeg, g_deg);
    cudaGetSymbolAddress((void**)&pFill, g_fill);
    cudaGetSymbolAddress((void**)&pAggpub, g_aggpub);

    cudaFuncSetAttribute(k_sage<32, true,  false>,
                         cudaFuncAttributeMaxDynamicSharedMemorySize, 32768);
    cudaFuncSetAttribute(k_sage<64, true,  false>,
                         cudaFuncAttributeMaxDynamicSharedMemorySize, 65536);
    cudaFuncSetAttribute(k_sage<64, false, true>,
                         cudaFuncAttributeMaxDynamicSharedMemorySize, 65536);

    cudaMemsetAsync(pDeg, 0, NODES * sizeof(int));
    cudaMemsetAsync(pFill, 0, NODES * sizeof(int));
    cudaMemsetAsync(pAggpub, 0xFF, SCAN_NB * sizeof(int));   // -1 sentinel

    // x->fp16 + hist (merged), then scan + fill
    k_cvthist<<<(EDGES + 255) / 256, 256>>>((const float2*)x, pHX, dst);
    k_scanlb<<<SCAN_NB, 1024>>>();
    k_fill<<<(EDGES + 255) / 256, 256>>>(src, dst);

    const int GRID = (NODES + 63) / 64;   // 1563

    // layer 0: 32 -> 64, relu (fp16 gather of x, fp32 own)
    k_sage<32, true,  false><<<GRID, 256, 32768>>>(x, pHX, Wn0, bn0, Wr0,
            nullptr, nullptr, nullptr, nullptr, pH0, pHH0, nullptr);
    // layer 1: 64 -> 64, relu
    k_sage<64, true,  false><<<GRID, 256, 65536>>>(pH0, pHH0, Wn1, bn1, Wr1,
            nullptr, nullptr, nullptr, nullptr, pH1, pHH1, nullptr);
    // layer 2: 64 -> 64, no relu, predictor fused
    k_sage<64, false, true ><<<GRID, 256, 65536>>>(pH1, pHH1, Wn2, bn2, Wr2,
            Wp1, bp1, Wp2, bp2, nullptr, nullptr, out);

    (void)in_sizes; (void)n_in; (void)out_size;
}